// round 13
// baseline (speedup 1.0000x reference)
#include <cuda_runtime.h>
#include <cuda_bf16.h>
#include <math.h>
#include <stdint.h>

// ============================================================================
// ODE-RNN: B=128, F=512, I=128, H=512, O=1, NSTEP=5
//
// R13 vs R12 (21.9 ms; fma=22.9% => 72% of each phase was exposed overhead):
//  * 16 groups x 8 samples; each CTA runs TWO groups (same columns -> weight
//    registers shared). While group q0 computes, q1's barrier completes and
//    its tile streams in via cp.async -> barrier/staging latency hidden.
//  * activation staging via cp.async.cg (L2-direct, async) + wait_group.
//  * single dual-counter wait per phase (both spins overlapped, 1 L2 trip).
//  * weights W1/W2 in registers (128 regs, shared by both groups), Whh in
//    SMEM; flush-free red.release barrier (from R11/R12).
// ============================================================================

#define BB     128
#define FF     512
#define IDIM   128
#define HH     512
#define NSTEPS 5
#define NGRP   16    // batch groups
#define BG     8     // samples per group
#define NC     16    // column CTAs per group
#define HC     32    // columns per CTA
#define NTHR   256
#define WPC    8     // warps per CTA
#define KW     64    // k-slice width per warp
#define BARN   (NC * WPC)   // barrier arrivals per phase per group

// ---------------- device scratch (no cudaMalloc allowed) -------------------
__device__ float    g_xproj[(size_t)FF * BB * HH];  // 128 MiB
__device__ float    g_h[NGRP * BG * HH];
__device__ float    g_a[NGRP * BG * HH];
__device__ float    g_part[NC * BB];
__device__ unsigned g_ctr[NGRP * 32];

// ---------------- dynamic SMEM layout (float offsets) ----------------------
#define SM_HB0  0
#define SM_HB1  (BG * HH)                    //  4096
#define SM_WHH  (2 * BG * HH)                //  8192
#define SM_RED  (SM_WHH + (HH / 4) * HC * 4) // 24576
#define SM_SC   (SM_RED + BG * WPC * HC)     // 26624
#define SM_TOT  ((SM_SC + 2 * BG) * 4)       // 106,560 bytes

// ---------------- packed f32x2 helpers -------------------------------------
__device__ __forceinline__ unsigned long long fma2(unsigned long long a,
                                                   unsigned long long b,
                                                   unsigned long long c) {
    unsigned long long d;
    asm("fma.rn.f32x2 %0, %1, %2, %3;" : "=l"(d) : "l"(a), "l"(b), "l"(c));
    return d;
}
__device__ __forceinline__ float upsum(unsigned long long v) {
    float lo, hi;
    asm("mov.b64 {%0, %1}, %2;" : "=f"(lo), "=f"(hi) : "l"(v));
    return lo + hi;
}

// ---------------- flush-free barrier primitives ------------------------------
__device__ __forceinline__ void arrive(unsigned* ctr, int lane) {
    __syncwarp();   // memory-sync among lanes: warp's stores ordered
    if (lane == 0)
        asm volatile("red.release.gpu.global.add.u32 [%0], 1;" :: "l"(ctr) : "memory");
}

__device__ __forceinline__ void wait2(unsigned* c0, unsigned* c1,
                                      unsigned target, int tid) {
    if (tid == 0) {
        unsigned v0, v1;
        do {  // both counter loads in flight together: one L2 round-trip
            asm volatile("ld.relaxed.gpu.global.u32 %0, [%1];"
                         : "=r"(v0) : "l"(c0) : "memory");
            asm volatile("ld.relaxed.gpu.global.u32 %0, [%1];"
                         : "=r"(v1) : "l"(c1) : "memory");
        } while (v0 < target || v1 < target);
    }
    __syncthreads();
}

// ---------------- async stage: 8x512 fp32 tile, L2 -> SMEM ------------------
__device__ __forceinline__ void stage_async(const float* src, float* dst, int tid) {
    unsigned    ds = (unsigned)__cvta_generic_to_shared(dst) + tid * 16;
    const char* gs = (const char*)src + (size_t)tid * 16;
#pragma unroll
    for (int it = 0; it < 4; ++it)
        asm volatile("cp.async.cg.shared.global [%0], [%1], 16;"
                     :: "r"(ds + it * NTHR * 16), "l"(gs + (size_t)it * NTHR * 16));
    asm volatile("cp.async.commit_group;" ::: "memory");
}
#define CP_WAIT1() asm volatile("cp.async.wait_group 1;" ::: "memory")
#define CP_WAIT0() asm volatile("cp.async.wait_group 0;" ::: "memory")

// ---------------- GEMM cores (8 rows, k-slice of 64) ------------------------
__device__ __forceinline__ void gemm8_reg(const unsigned long long* wreg,
                                          const float* __restrict__ hb, int k0,
                                          float part[BG]) {
    unsigned long long acc[BG];
#pragma unroll
    for (int r = 0; r < BG; ++r) acc[r] = 0ull;
#pragma unroll
    for (int k4 = 0; k4 < KW / 4; ++k4) {
#pragma unroll
        for (int r = 0; r < BG; ++r) {
            ulonglong2 hv = *(const ulonglong2*)(hb + r * HH + k0 + 4 * k4);
            acc[r] = fma2(wreg[2 * k4],     hv.x, acc[r]);
            acc[r] = fma2(wreg[2 * k4 + 1], hv.y, acc[r]);
        }
    }
#pragma unroll
    for (int r = 0; r < BG; ++r) part[r] = upsum(acc[r]);
}

__device__ __forceinline__ void gemm8_smem(const float* __restrict__ wsm,
                                           int w, int l,
                                           const float* __restrict__ hb, int k0,
                                           float part[BG]) {
    unsigned long long acc[BG];
#pragma unroll
    for (int r = 0; r < BG; ++r) acc[r] = 0ull;
#pragma unroll
    for (int k4 = 0; k4 < KW / 4; ++k4) {
        ulonglong2 wv = *(const ulonglong2*)(wsm + (((w * 16 + k4) * HC + l) << 2));
#pragma unroll
        for (int r = 0; r < BG; ++r) {
            ulonglong2 hv = *(const ulonglong2*)(hb + r * HH + k0 + 4 * k4);
            acc[r] = fma2(wv.x, hv.x, acc[r]);
            acc[r] = fma2(wv.y, hv.y, acc[r]);
        }
    }
#pragma unroll
    for (int r = 0; r < BG; ++r) part[r] = upsum(acc[r]);
}

// split-k reduction: thread (w,l) ends owning (row w, col l)
__device__ __forceinline__ void reduce8(float* red, const float part[BG],
                                        int w, int l, float& s) {
#pragma unroll
    for (int r = 0; r < BG; ++r)
        red[(r * WPC + w) * HC + l] = part[r];
    __syncthreads();
    s = 0.0f;
#pragma unroll
    for (int wp = 0; wp < WPC; ++wp)
        s += red[(w * WPC + wp) * HC + l];
}

// ============================================================================
__global__ void pad_kernel() {
    if (threadIdx.x > 1024) g_ctr[0] = 1u;  // never true
}

__global__ void init_kernel() {
    int t = blockIdx.x * blockDim.x + threadIdx.x;
    if (t < NGRP * 32) g_ctr[t] = 0u;
    for (int i = t; i < NGRP * BG * HH; i += gridDim.x * blockDim.x)
        g_h[i] = 0.0f;
}

// ============================================================================
// xproj[f][b][h] = x[b,f,:] @ Wih^T + bih + bhh
// ============================================================================
__global__ void __launch_bounds__(256) xproj_kernel(const float* __restrict__ x,
                                                    const float* __restrict__ Wih,
                                                    const float* __restrict__ bih,
                                                    const float* __restrict__ bhh) {
    __shared__ float4 xs[16 * (IDIM / 4)];
    const int tid   = threadIdx.x;
    const int m0    = blockIdx.x * 16;
    const int j     = blockIdx.y * 128 + (tid & 127);
    const int rbase = (tid >> 7) * 8;

    const float4* xg = (const float4*)(x + (size_t)m0 * IDIM);
#pragma unroll
    for (int it = 0; it < 2; ++it) xs[tid + it * 256] = xg[tid + it * 256];
    __syncthreads();

    const float4* wr = (const float4*)(Wih + (size_t)j * IDIM);
    float acc[8];
#pragma unroll
    for (int r = 0; r < 8; ++r) acc[r] = 0.0f;

#pragma unroll 4
    for (int k = 0; k < IDIM / 4; ++k) {
        float4 wv = __ldg(wr + k);
#pragma unroll
        for (int r = 0; r < 8; ++r) {
            float4 xv = xs[(rbase + r) * (IDIM / 4) + k];
            acc[r] += wv.x * xv.x + wv.y * xv.y + wv.z * xv.z + wv.w * xv.w;
        }
    }
    const float bias = __ldg(bih + j) + __ldg(bhh + j);
#pragma unroll
    for (int r = 0; r < 8; ++r) {
        int mm = m0 + rbase + r;
        int b  = mm >> 9;
        int f  = mm & 511;
        g_xproj[((size_t)f * BB + b) * HH + j] = acc[r] + bias;
    }
}

// ============================================================================
// persistent recurrence: 128 CTAs = 8 group-pairs x 16 col-CTAs
// ============================================================================
__global__ void __launch_bounds__(NTHR, 1)
odernn_persist(const float* __restrict__ tp,
               const float* __restrict__ W1, const float* __restrict__ b1,
               const float* __restrict__ W2, const float* __restrict__ b2,
               const float* __restrict__ Whh, const float* __restrict__ Wc) {
    extern __shared__ float smem[];
    float* hb0  = smem + SM_HB0;
    float* hb1  = smem + SM_HB1;
    float* whhs = smem + SM_WHH;
    float* red  = smem + SM_RED;
    float* scs  = smem + SM_SC;

    const int tid = threadIdx.x;
    const int m   = blockIdx.x >> 4;   // group pair 0..7
    const int c   = blockIdx.x & 15;   // column block
    const int w   = tid >> 5;          // warp = k-slice AND owned row
    const int l   = tid & 31;          // lane = column
    const int j   = c * HC + l;
    const int k0  = w * KW;
    const int g0  = 2 * m, g1 = 2 * m + 1;

    float*    hg0  = g_h + g0 * BG * HH;
    float*    hg1  = g_h + g1 * BG * HH;
    float*    ag0  = g_a + g0 * BG * HH;
    float*    ag1  = g_a + g1 * BG * HH;
    unsigned* ctr0 = &g_ctr[g0 * 32];
    unsigned* ctr1 = &g_ctr[g1 * 32];

    // ---- W1/W2 k-slices -> registers (shared by both groups) ----
    unsigned long long w1r[KW / 2], w2r[KW / 2];
#pragma unroll
    for (int i = 0; i < KW / 2; ++i) {
        w1r[i] = *(const unsigned long long*)(W1 + (size_t)j * HH + k0 + 2 * i);
        w2r[i] = *(const unsigned long long*)(W2 + (size_t)j * HH + k0 + 2 * i);
    }
    // ---- Whh slice -> SMEM (k4-chunked, conflict-free) ----
#pragma unroll
    for (int i = 0; i < 16; ++i) {
        int k4g = w * 16 + i;
        float4 v = *(const float4*)(Whh + (size_t)j * HH + 4 * k4g);
        *(float4*)(whhs + ((k4g * HC + l) << 2)) = v;
    }
    const float b1j = __ldg(b1 + j);
    const float b2j = __ldg(b2 + j);
    __syncthreads();

    float hown0 = 0.0f, hown1 = 0.0f;   // (row w, col j) of h per group
    float fs0 = 0.0f, fs1 = 0.0f;       // running sums for mean over f
    unsigned ph = 0;                    // completed-phase counter
    float part[BG], sum;

    for (int f = 0; f < FF; ++f) {
        if (tid < 2 * BG) {
            int q = tid >> 3, r = tid & 7;
            int b = (2 * m + q) * BG + r;
            float d = (f == 0) ? 0.0f
                               : (__ldcg(tp + b * FF + f) - __ldcg(tp + b * FF + f - 1));
            scs[q * BG + r] = d * (1.0f / NSTEPS);
        }
        // scs published by the next syncthreads (inside wait2)

        for (int s5 = 0; s5 < NSTEPS; ++s5) {
            // ======== phase A: a = relu(h @ W1^T + b1) ========
            wait2(ctr0, ctr1, ph * BARN, tid);
            stage_async(hg0, hb0, tid);
            stage_async(hg1, hb1, tid);
            CP_WAIT1(); __syncthreads();
            gemm8_reg(w1r, hb0, k0, part);
            reduce8(red, part, w, l, sum);
            __stcg(ag0 + w * HH + j, fmaxf(sum + b1j, 0.0f));
            arrive(ctr0, l);
            CP_WAIT0(); __syncthreads();
            gemm8_reg(w1r, hb1, k0, part);
            reduce8(red, part, w, l, sum);
            __stcg(ag1 + w * HH + j, fmaxf(sum + b1j, 0.0f));
            arrive(ctr1, l);
            ++ph;

            // ======== phase B: h += (a @ W2^T + b2) * scale ========
            wait2(ctr0, ctr1, ph * BARN, tid);
            stage_async(ag0, hb0, tid);
            stage_async(ag1, hb1, tid);
            CP_WAIT1(); __syncthreads();
            gemm8_reg(w2r, hb0, k0, part);
            reduce8(red, part, w, l, sum);
            hown0 += (sum + b2j) * scs[w];
            __stcg(hg0 + w * HH + j, hown0);
            arrive(ctr0, l);
            CP_WAIT0(); __syncthreads();
            gemm8_reg(w2r, hb1, k0, part);
            reduce8(red, part, w, l, sum);
            hown1 += (sum + b2j) * scs[BG + w];
            __stcg(hg1 + w * HH + j, hown1);
            arrive(ctr1, l);
            ++ph;
        }

        // ======== phase C: h = tanh(xproj + hp @ Whh^T) ========
        wait2(ctr0, ctr1, ph * BARN, tid);
        {
            float xp0 = __ldcg(g_xproj + ((size_t)f * BB + g0 * BG + w) * HH + j);
            float xp1 = __ldcg(g_xproj + ((size_t)f * BB + g1 * BG + w) * HH + j);
            stage_async(hg0, hb0, tid);
            stage_async(hg1, hb1, tid);
            CP_WAIT1(); __syncthreads();
            gemm8_smem(whhs, w, l, hb0, k0, part);
            reduce8(red, part, w, l, sum);
            hown0 = tanhf(sum + xp0);
            fs0 += hown0;
            __stcg(hg0 + w * HH + j, hown0);
            arrive(ctr0, l);
            CP_WAIT0(); __syncthreads();
            gemm8_smem(whhs, w, l, hb1, k0, part);
            reduce8(red, part, w, l, sum);
            hown1 = tanhf(sum + xp1);
            fs1 += hown1;
            __stcg(hg1 + w * HH + j, hown1);
            arrive(ctr1, l);
        }
        ++ph;
    }

    // ---- classifier partials: warp w = sample row w, lanes = 32 columns ----
    const float wcj = __ldg(Wc + j);
    float p0 = fs0 * wcj * (1.0f / FF);
    float p1 = fs1 * wcj * (1.0f / FF);
#pragma unroll
    for (int o = 16; o; o >>= 1) {
        p0 += __shfl_xor_sync(0xffffffffu, p0, o);
        p1 += __shfl_xor_sync(0xffffffffu, p1, o);
    }
    if (l == 0) {
        g_part[c * BB + g0 * BG + w] = p0;
        g_part[c * BB + g1 * BG + w] = p1;
    }
}

// ============================================================================
__global__ void finalize_kernel(const float* __restrict__ bc, float* __restrict__ out) {
    int b = threadIdx.x;
    float s = __ldg(bc);
#pragma unroll
    for (int c = 0; c < NC; ++c) s += g_part[c * BB + b];
    out[b] = 1.0f / (1.0f + expf(-s));
}

// ============================================================================
extern "C" void kernel_launch(void* const* d_in, const int* in_sizes, int n_in,
                              void* d_out, int out_size) {
    const float* x   = (const float*)d_in[0];
    const float* tp  = (const float*)d_in[1];
    const float* W1  = (const float*)d_in[2];
    const float* b1  = (const float*)d_in[3];
    const float* W2  = (const float*)d_in[4];
    const float* b2  = (const float*)d_in[5];
    const float* Wih = (const float*)d_in[6];
    const float* Whh = (const float*)d_in[7];
    const float* bih = (const float*)d_in[8];
    const float* bhh = (const float*)d_in[9];
    const float* Wc  = (const float*)d_in[10];
    const float* bc  = (const float*)d_in[11];
    float* out = (float*)d_out;

    cudaFuncSetAttribute(odernn_persist,
                         cudaFuncAttributeMaxDynamicSharedMemorySize, SM_TOT);

    pad_kernel<<<1, 32>>>();   // keeps ncu capture window on odernn_persist

    init_kernel<<<64, 256>>>();

    dim3 gx(BB * FF / 16, HH / 128);
    xproj_kernel<<<gx, 256>>>(x, Wih, bih, bhh);

    odernn_persist<<<128, NTHR, SM_TOT>>>(tp, W1, b1, W2, b2, Whh, Wc);

    finalize_kernel<<<1, BB>>>(bc, out);

    (void)in_sizes; (void)n_in; (void)out_size;
}

// round 14
// speedup vs baseline: 1.1298x; 1.1298x over previous
#include <cuda_runtime.h>
#include <cuda_bf16.h>
#include <math.h>
#include <stdint.h>

// ============================================================================
// ODE-RNN: B=128, F=512, I=128, H=512, O=1, NSTEP=5
//
// R14 vs R13 (24.0 ms) / R12 (21.9 ms):
//  * warp specialization: 8 compute warps + 1 comm warp (288 thr/CTA).
//    comm warp = counter spin + cp.async.cg tile stage + named-barrier
//    release. Compute warps never wait on L2; barrier+stage latency of
//    group q1 hides under group q0's compute (true stagger, unlike R13).
//  * W1 in registers; W2 and Whh in SMEM (k4-chunked, conflict-free
//    LDS.128) to fit the 224-reg/thread budget at 288 threads.
//  * flush-free release-red barrier + .cg data path (proven R11-R13).
// ============================================================================

#define BB     128
#define FF     512
#define IDIM   128
#define HH     512
#define NSTEPS 5
#define NGRP   16    // batch groups
#define BG     8     // samples per group
#define NC     16    // column CTAs per group
#define HC     32    // columns per CTA
#define NCW    8     // compute warps
#define NTHR   (32 * (NCW + 1))   // 288
#define KW     64    // k-slice width per compute warp
#define BARN   (NC * NCW)         // 128 arrivals per group per phase

// ---------------- device scratch (no cudaMalloc allowed) -------------------
__device__ float    g_xproj[(size_t)FF * BB * HH];  // 128 MiB
__device__ float    g_h[NGRP * BG * HH];
__device__ float    g_a[NGRP * BG * HH];
__device__ float    g_part[NC * BB];
__device__ unsigned g_ctr[NGRP * 32];

// ---------------- dynamic SMEM layout (float offsets) ----------------------
#define SM_HB0  0
#define SM_HB1  (BG * HH)                     //  4096
#define SM_WHH  (2 * BG * HH)                 //  8192
#define SM_W2   (SM_WHH + (HH / 4) * HC * 4)  // 24576
#define SM_RED  (SM_W2  + (HH / 4) * HC * 4)  // 40960
#define SM_SC   (SM_RED + BG * NCW * HC)      // 43008
#define SM_TOT  ((SM_SC + 2 * BG) * 4)        // 172,096 bytes

// ---------------- packed f32x2 helpers -------------------------------------
__device__ __forceinline__ unsigned long long fma2(unsigned long long a,
                                                   unsigned long long b,
                                                   unsigned long long c) {
    unsigned long long d;
    asm("fma.rn.f32x2 %0, %1, %2, %3;" : "=l"(d) : "l"(a), "l"(b), "l"(c));
    return d;
}
__device__ __forceinline__ float upsum(unsigned long long v) {
    float lo, hi;
    asm("mov.b64 {%0, %1}, %2;" : "=f"(lo), "=f"(hi) : "l"(v));
    return lo + hi;
}

// ---------------- named barriers --------------------------------------------
#define BARX(id, cnt) asm volatile("bar.sync %0, %1;" :: "r"(id), "r"(cnt) : "memory")

// ---------------- flush-free arrival ----------------------------------------
__device__ __forceinline__ void arrive(unsigned* ctr, int lane) {
    __syncwarp();
    if (lane == 0)
        asm volatile("red.release.gpu.global.add.u32 [%0], 1;" :: "l"(ctr) : "memory");
}

// ---------------- comm-warp primitives --------------------------------------
__device__ __forceinline__ void comm_wait(unsigned* ctr, unsigned target, int cwl) {
    if (cwl == 0) {
        unsigned v;
        do {
            asm volatile("ld.relaxed.gpu.global.u32 %0, [%1];"
                         : "=r"(v) : "l"(ctr) : "memory");
        } while (v < target);
    }
    __syncwarp();
}
// stage 8x512 fp32 (16 KB, contiguous) into SMEM via cp.async.cg (L2-direct)
__device__ __forceinline__ void comm_stage(const float* src, float* dst, int cwl) {
    unsigned    ds = (unsigned)__cvta_generic_to_shared(dst) + cwl * 16;
    const char* gs = (const char*)src + cwl * 16;
#pragma unroll
    for (int i = 0; i < 32; ++i)
        asm volatile("cp.async.cg.shared.global [%0], [%1], 16;"
                     :: "r"(ds + i * 512), "l"(gs + (size_t)i * 512));
    asm volatile("cp.async.commit_group;" ::: "memory");
    asm volatile("cp.async.wait_group 0;" ::: "memory");
}

// ---------------- GEMM cores (8 rows, per-warp k-slice of 64) ---------------
__device__ __forceinline__ void gemm8_reg(const unsigned long long* wreg,
                                          const float* __restrict__ hb, int k0,
                                          float part[BG]) {
    unsigned long long acc[BG];
#pragma unroll
    for (int r = 0; r < BG; ++r) acc[r] = 0ull;
#pragma unroll
    for (int k4 = 0; k4 < KW / 4; ++k4) {
#pragma unroll
        for (int r = 0; r < BG; ++r) {
            ulonglong2 hv = *(const ulonglong2*)(hb + r * HH + k0 + 4 * k4);
            acc[r] = fma2(wreg[2 * k4],     hv.x, acc[r]);
            acc[r] = fma2(wreg[2 * k4 + 1], hv.y, acc[r]);
        }
    }
#pragma unroll
    for (int r = 0; r < BG; ++r) part[r] = upsum(acc[r]);
}

__device__ __forceinline__ void gemm8_smem(const float* __restrict__ wsm,
                                           int w, int l,
                                           const float* __restrict__ hb, int k0,
                                           float part[BG]) {
    unsigned long long acc[BG];
#pragma unroll
    for (int r = 0; r < BG; ++r) acc[r] = 0ull;
#pragma unroll
    for (int k4 = 0; k4 < KW / 4; ++k4) {
        ulonglong2 wv = *(const ulonglong2*)(wsm + (((w * 16 + k4) * HC + l) << 2));
#pragma unroll
        for (int r = 0; r < BG; ++r) {
            ulonglong2 hv = *(const ulonglong2*)(hb + r * HH + k0 + 4 * k4);
            acc[r] = fma2(wv.x, hv.x, acc[r]);
            acc[r] = fma2(wv.y, hv.y, acc[r]);
        }
    }
#pragma unroll
    for (int r = 0; r < BG; ++r) part[r] = upsum(acc[r]);
}

// split-k reduction among the 8 COMPUTE warps only (named barrier 3, 256 thr)
__device__ __forceinline__ void reduce8(float* red, const float part[BG],
                                        int w, int l, float& s) {
#pragma unroll
    for (int r = 0; r < BG; ++r)
        red[(r * NCW + w) * HC + l] = part[r];
    BARX(3, 256);
    s = 0.0f;
#pragma unroll
    for (int wp = 0; wp < NCW; ++wp)
        s += red[(w * NCW + wp) * HC + l];
}

// ============================================================================
__global__ void pad_kernel() {
    if (threadIdx.x > 1024) g_ctr[0] = 1u;  // never true
}

__global__ void init_kernel() {
    int t = blockIdx.x * blockDim.x + threadIdx.x;
    if (t < NGRP * 32) g_ctr[t] = 0u;
    for (int i = t; i < NGRP * BG * HH; i += gridDim.x * blockDim.x)
        g_h[i] = 0.0f;
}

// ============================================================================
// xproj[f][b][h] = x[b,f,:] @ Wih^T + bih + bhh
// ============================================================================
__global__ void __launch_bounds__(256) xproj_kernel(const float* __restrict__ x,
                                                    const float* __restrict__ Wih,
                                                    const float* __restrict__ bih,
                                                    const float* __restrict__ bhh) {
    __shared__ float4 xs[16 * (IDIM / 4)];
    const int tid   = threadIdx.x;
    const int m0    = blockIdx.x * 16;
    const int j     = blockIdx.y * 128 + (tid & 127);
    const int rbase = (tid >> 7) * 8;

    const float4* xg = (const float4*)(x + (size_t)m0 * IDIM);
#pragma unroll
    for (int it = 0; it < 2; ++it) xs[tid + it * 256] = xg[tid + it * 256];
    __syncthreads();

    const float4* wr = (const float4*)(Wih + (size_t)j * IDIM);
    float acc[8];
#pragma unroll
    for (int r = 0; r < 8; ++r) acc[r] = 0.0f;

#pragma unroll 4
    for (int k = 0; k < IDIM / 4; ++k) {
        float4 wv = __ldg(wr + k);
#pragma unroll
        for (int r = 0; r < 8; ++r) {
            float4 xv = xs[(rbase + r) * (IDIM / 4) + k];
            acc[r] += wv.x * xv.x + wv.y * xv.y + wv.z * xv.z + wv.w * xv.w;
        }
    }
    const float bias = __ldg(bih + j) + __ldg(bhh + j);
#pragma unroll
    for (int r = 0; r < 8; ++r) {
        int mm = m0 + rbase + r;
        int b  = mm >> 9;
        int f  = mm & 511;
        g_xproj[((size_t)f * BB + b) * HH + j] = acc[r] + bias;
    }
}

// ============================================================================
// persistent recurrence: 128 CTAs = 8 group-pairs x 16 col-CTAs
//   warps 0-7: compute (k-slices).   warp 8: comm (spin+stage+release).
// ============================================================================
__global__ void __launch_bounds__(NTHR, 1)
odernn_persist(const float* __restrict__ tp,
               const float* __restrict__ W1, const float* __restrict__ b1,
               const float* __restrict__ W2, const float* __restrict__ b2,
               const float* __restrict__ Whh, const float* __restrict__ Wc) {
    extern __shared__ float smem[];
    float* hb0  = smem + SM_HB0;
    float* hb1  = smem + SM_HB1;
    float* whhs = smem + SM_WHH;
    float* w2s  = smem + SM_W2;
    float* red  = smem + SM_RED;
    float* scs  = smem + SM_SC;

    const int tid = threadIdx.x;
    const int m   = blockIdx.x >> 4;   // group pair 0..7
    const int c   = blockIdx.x & 15;   // column block
    const int w   = tid >> 5;          // warp id (8 = comm)
    const int l   = tid & 31;
    const int g0  = 2 * m, g1 = 2 * m + 1;

    float*    hg0  = g_h + g0 * BG * HH;
    float*    hg1  = g_h + g1 * BG * HH;
    float*    ag0  = g_a + g0 * BG * HH;
    float*    ag1  = g_a + g1 * BG * HH;
    unsigned* ctr0 = &g_ctr[g0 * 32];
    unsigned* ctr1 = &g_ctr[g1 * 32];

    // ------------------- setup (all 288 threads) ---------------------------
    unsigned long long w1r[KW / 2];
    float b1j = 0.0f, b2j = 0.0f;
    int j = 0, k0 = 0;
    if (w < NCW) {
        j  = c * HC + l;
        k0 = w * KW;
#pragma unroll
        for (int i = 0; i < KW / 2; ++i)
            w1r[i] = *(const unsigned long long*)(W1 + (size_t)j * HH + k0 + 2 * i);
        // W2 and Whh slices -> SMEM (k4-chunked, conflict-free)
#pragma unroll
        for (int i = 0; i < 16; ++i) {
            int k4g = w * 16 + i;
            *(float4*)(whhs + ((k4g * HC + l) << 2)) =
                *(const float4*)(Whh + (size_t)j * HH + 4 * k4g);
            *(float4*)(w2s + ((k4g * HC + l) << 2)) =
                *(const float4*)(W2 + (size_t)j * HH + 4 * k4g);
        }
        b1j = __ldg(b1 + j);
        b2j = __ldg(b2 + j);
    }
    __syncthreads();   // one full-CTA sync before the specialized loops

    if (w == NCW) {
        // =================== COMM WARP =====================================
        const int cwl = l;
        unsigned q = 0;   // global phase index
        for (int f = 0; f < FF; ++f) {
            for (int ph = 0; ph < 2 * NSTEPS + 1; ++ph) {
                // which activation buffer feeds this phase?
                const float* s0 = (ph & 1) ? ag0 : hg0;   // odd = phase B
                const float* s1 = (ph & 1) ? ag1 : hg1;
                if (ph == 2 * NSTEPS) { s0 = hg0; s1 = hg1; }  // phase C

                comm_wait(ctr0, q * BARN, cwl);
                comm_stage(s0, hb0, cwl);
                if (ph == 0 && cwl < 2 * BG) {   // per-step Euler scales
                    int qq = cwl >> 3, r = cwl & 7;
                    int b = (2 * m + qq) * BG + r;
                    float d = (f == 0) ? 0.0f
                                       : (__ldcg(tp + b * FF + f) - __ldcg(tp + b * FF + f - 1));
                    scs[qq * BG + r] = d * (1.0f / NSTEPS);
                }
                BARX(1, NTHR);

                comm_wait(ctr1, q * BARN, cwl);
                comm_stage(s1, hb1, cwl);
                BARX(2, NTHR);
                ++q;
            }
        }
    } else {
        // =================== COMPUTE WARPS =================================
        float hown0 = 0.0f, hown1 = 0.0f;
        float fs0 = 0.0f, fs1 = 0.0f;
        float part[BG], sum;

        for (int f = 0; f < FF; ++f) {
            for (int s5 = 0; s5 < NSTEPS; ++s5) {
                // ---- phase A: a = relu(h @ W1^T + b1) ----
                BARX(1, NTHR);
                gemm8_reg(w1r, hb0, k0, part);
                reduce8(red, part, w, l, sum);
                __stcg(ag0 + w * HH + j, fmaxf(sum + b1j, 0.0f));
                arrive(ctr0, l);
                BARX(2, NTHR);
                gemm8_reg(w1r, hb1, k0, part);
                reduce8(red, part, w, l, sum);
                __stcg(ag1 + w * HH + j, fmaxf(sum + b1j, 0.0f));
                arrive(ctr1, l);

                // ---- phase B: h += (a @ W2^T + b2) * scale ----
                BARX(1, NTHR);
                gemm8_smem(w2s, w, l, hb0, k0, part);
                reduce8(red, part, w, l, sum);
                hown0 += (sum + b2j) * scs[w];
                __stcg(hg0 + w * HH + j, hown0);
                arrive(ctr0, l);
                BARX(2, NTHR);
                gemm8_smem(w2s, w, l, hb1, k0, part);
                reduce8(red, part, w, l, sum);
                hown1 += (sum + b2j) * scs[BG + w];
                __stcg(hg1 + w * HH + j, hown1);
                arrive(ctr1, l);
            }

            // ---- phase C: h = tanh(xproj + hp @ Whh^T) ----
            BARX(1, NTHR);
            {
                float xp0 = __ldcg(g_xproj + ((size_t)f * BB + g0 * BG + w) * HH + j);
                gemm8_smem(whhs, w, l, hb0, k0, part);
                reduce8(red, part, w, l, sum);
                hown0 = tanhf(sum + xp0);
                fs0 += hown0;
                __stcg(hg0 + w * HH + j, hown0);
                arrive(ctr0, l);
            }
            BARX(2, NTHR);
            {
                float xp1 = __ldcg(g_xproj + ((size_t)f * BB + g1 * BG + w) * HH + j);
                gemm8_smem(whhs, w, l, hb1, k0, part);
                reduce8(red, part, w, l, sum);
                hown1 = tanhf(sum + xp1);
                fs1 += hown1;
                __stcg(hg1 + w * HH + j, hown1);
                arrive(ctr1, l);
            }
        }

        // ---- classifier partials ----
        const float wcj = __ldg(Wc + j);
        float p0 = fs0 * wcj * (1.0f / FF);
        float p1 = fs1 * wcj * (1.0f / FF);
#pragma unroll
        for (int o = 16; o; o >>= 1) {
            p0 += __shfl_xor_sync(0xffffffffu, p0, o);
            p1 += __shfl_xor_sync(0xffffffffu, p1, o);
        }
        if (l == 0) {
            g_part[c * BB + g0 * BG + w] = p0;
            g_part[c * BB + g1 * BG + w] = p1;
        }
    }
}

// ============================================================================
__global__ void finalize_kernel(const float* __restrict__ bc, float* __restrict__ out) {
    int b = threadIdx.x;
    float s = __ldg(bc);
#pragma unroll
    for (int c = 0; c < NC; ++c) s += g_part[c * BB + b];
    out[b] = 1.0f / (1.0f + expf(-s));
}

// ============================================================================
extern "C" void kernel_launch(void* const* d_in, const int* in_sizes, int n_in,
                              void* d_out, int out_size) {
    const float* x   = (const float*)d_in[0];
    const float* tp  = (const float*)d_in[1];
    const float* W1  = (const float*)d_in[2];
    const float* b1  = (const float*)d_in[3];
    const float* W2  = (const float*)d_in[4];
    const float* b2  = (const float*)d_in[5];
    const float* Wih = (const float*)d_in[6];
    const float* Whh = (const float*)d_in[7];
    const float* bih = (const float*)d_in[8];
    const float* bhh = (const float*)d_in[9];
    const float* Wc  = (const float*)d_in[10];
    const float* bc  = (const float*)d_in[11];
    float* out = (float*)d_out;

    cudaFuncSetAttribute(odernn_persist,
                         cudaFuncAttributeMaxDynamicSharedMemorySize, SM_TOT);

    pad_kernel<<<1, 32>>>();   // keeps ncu capture window on odernn_persist

    init_kernel<<<64, 256>>>();

    dim3 gx(BB * FF / 16, HH / 128);
    xproj_kernel<<<gx, 256>>>(x, Wih, bih, bhh);

    odernn_persist<<<128, NTHR, SM_TOT>>>(tp, W1, b1, W2, b2, Whh, Wc);

    finalize_kernel<<<1, BB>>>(bc, out);

    (void)in_sizes; (void)n_in; (void)out_size;
}